// round 13
// baseline (speedup 1.0000x reference)
#include <cuda_runtime.h>
#include <cuda_bf16.h>

#define NN   100000
#define NE   1000000
#define NEX  (NE + NN)      // edges + self loops
#define NG   2048
#define FIN  128
#define HC   64
#define NEG_SLOPE 0.2f

// ---------------- scratch (device globals; no cudaMalloc allowed) -----------
__device__ float g_xl[NN * HC];        // lin_l(x)  [N,64]
__device__ float g_xr[NN * HC];        // lin_r(x)  [N,64]
__device__ int   g_off[NN + 1];        // degree -> exclusive offsets (in place)
__device__ int   g_cur[NN];            // scatter cursors
__device__ int   g_srcs[NEX];          // CSR: src node per incoming edge slot
__device__ float g_logit[NEX * 2];     // per-edge per-head attention logits
__device__ float g_h[NN * HC];         // conv output
__device__ float g_hs[NN];             // h . w_rel
__device__ float g_score[NN];          // SAG score
__device__ float g_gmax[NG];
__device__ float g_gsum[NG];
__device__ int   g_cnt[NG];
__device__ float g_gacc[NG * HC];
__device__ int   g_bsum[128];          // scan block sums

__device__ __forceinline__ void atomicMaxFloat(float* addr, float v) {
    if (v >= 0.0f) atomicMax((int*)addr, __float_as_int(v));
    else           atomicMin((unsigned int*)addr, __float_as_uint(v));
}

// ---------------- K0: init ---------------------------------------------------
__global__ void k_init() {
    int i = blockIdx.x * blockDim.x + threadIdx.x;
    if (i < NN) g_off[i] = 1;                 // self loop pre-counted
    if (i < NG) {
        g_gmax[i] = __int_as_float(0xff800000);  // -inf
        g_gsum[i] = 0.0f;
        g_cnt[i]  = 0;
    }
    if (i < NG * HC) g_gacc[i] = 0.0f;
    if (i == 0) g_off[NN] = NEX;
}

// ---------------- K1: xl = x@W_l, xr = x@W_r ---------------------------------
// block: 256 thr; tile: 32 rows x 128 output cols (cols 0-63 -> xl, 64-127 -> xr)
// thread (cg = tid&31, rg = tid>>5): 4 rows x 4 cols register tile.
__global__ void __launch_bounds__(256) k_gemm(const float* __restrict__ x,
                                              const float* __restrict__ Wl,
                                              const float* __restrict__ Wr) {
    __shared__ float sx[32 * 128];   // 16KB
    const int tid = threadIdx.x;
    const int cg  = tid & 31;
    const int rg  = tid >> 5;
    const float* Wmat = (cg < 16) ? Wl : Wr;
    float* outp = (cg < 16) ? g_xl : g_xr;
    const int col = (cg & 15) * 4;

    for (int tile = blockIdx.x; tile < NN / 32; tile += gridDim.x) {
        const int row0 = tile * 32;
        __syncthreads();
        {   // stage x tile (coalesced float4)
            const float4* xg = (const float4*)(x + (size_t)row0 * FIN);
            float4* sx4 = (float4*)sx;
            #pragma unroll
            for (int idx = tid; idx < 1024; idx += 256) sx4[idx] = xg[idx];
        }
        __syncthreads();

        float acc[4][4];
        #pragma unroll
        for (int j = 0; j < 4; j++)
            #pragma unroll
            for (int c = 0; c < 4; c++) acc[j][c] = 0.0f;

        #pragma unroll 8
        for (int k = 0; k < FIN; k++) {
            const float4 w = __ldg((const float4*)(Wmat + k * HC + col));
            #pragma unroll
            for (int j = 0; j < 4; j++) {
                const float xv = sx[(rg * 4 + j) * FIN + k];   // warp broadcast
                acc[j][0] = fmaf(xv, w.x, acc[j][0]);
                acc[j][1] = fmaf(xv, w.y, acc[j][1]);
                acc[j][2] = fmaf(xv, w.z, acc[j][2]);
                acc[j][3] = fmaf(xv, w.w, acc[j][3]);
            }
        }
        #pragma unroll
        for (int j = 0; j < 4; j++) {
            const int row = row0 + rg * 4 + j;
            *((float4*)(outp + (size_t)row * HC + col)) =
                make_float4(acc[j][0], acc[j][1], acc[j][2], acc[j][3]);
        }
    }
}

// ---------------- K2: in-degree histogram ------------------------------------
__global__ void k_hist(const int* __restrict__ ei) {
    int e = blockIdx.x * blockDim.x + threadIdx.x;
    if (e < NE) atomicAdd(&g_off[ei[NE + e]], 1);
}

// ---------------- K3-K5: exclusive scan of degrees ---------------------------
__global__ void __launch_bounds__(1024) k_scan1() {
    __shared__ int sm[1024];
    const int tid = threadIdx.x;
    const int gid = blockIdx.x * 1024 + tid;
    int v = (gid < NN) ? g_off[gid] : 0;
    sm[tid] = v;
    __syncthreads();
    #pragma unroll
    for (int o = 1; o < 1024; o <<= 1) {
        int t = (tid >= o) ? sm[tid - o] : 0;
        __syncthreads();
        sm[tid] += t;
        __syncthreads();
    }
    if (gid < NN) g_off[gid] = sm[tid] - v;        // exclusive
    if (tid == 1023) g_bsum[blockIdx.x] = sm[1023];
}

__global__ void k_scan2() {
    __shared__ int sm[128];
    const int tid = threadIdx.x;
    int v = (tid < 98) ? g_bsum[tid] : 0;
    sm[tid] = v;
    __syncthreads();
    #pragma unroll
    for (int o = 1; o < 128; o <<= 1) {
        int t = (tid >= o) ? sm[tid - o] : 0;
        __syncthreads();
        sm[tid] += t;
        __syncthreads();
    }
    if (tid < 98) g_bsum[tid] = sm[tid] - v;       // exclusive block offsets
}

__global__ void k_scan3() {
    int gid = blockIdx.x * blockDim.x + threadIdx.x;
    if (gid < NN) {
        int o = g_off[gid] + g_bsum[gid >> 10];
        g_off[gid] = o;
        g_cur[gid] = o;
    }
}

// ---------------- K6: scatter edges into dst-CSR -----------------------------
__global__ void k_scatter(const int* __restrict__ ei) {
    int e = blockIdx.x * blockDim.x + threadIdx.x;
    if (e < NEX) {
        int s, d;
        if (e < NE) { s = ei[e]; d = ei[NE + e]; }
        else        { s = d = e - NE; }            // self loop
        int pos = atomicAdd(&g_cur[d], 1);
        g_srcs[pos] = s;
    }
}

// ---------------- K7: GATv2 attention, warp per dst node ---------------------
// lane l owns features (h=0,c=l) and (h=1,c=l) i.e. flat idx l and l+32.
__global__ void __launch_bounds__(256) k_attn(const float* __restrict__ att,
                                              const float* __restrict__ bias,
                                              const float* __restrict__ w_rel,
                                              const float* __restrict__ w_root,
                                              const float* __restrict__ b_score) {
    const int w    = (blockIdx.x * blockDim.x + threadIdx.x) >> 5;
    const int lane = threadIdx.x & 31;
    if (w >= NN) return;
    const int i   = w;
    const int beg = g_off[i];
    const int end = g_off[i + 1];

    const float xr0 = g_xr[i * HC + lane];
    const float xr1 = g_xr[i * HC + 32 + lane];
    const float a0  = att[lane];
    const float a1  = att[32 + lane];

    float m0 = -INFINITY, m1 = -INFINITY;
    // pass 1: logits + per-head max
    for (int k = beg; k < end; k++) {
        const int s = g_srcs[k];
        float v0 = g_xl[s * HC + lane]      + xr0;
        float v1 = g_xl[s * HC + 32 + lane] + xr1;
        v0 = (v0 > 0.0f) ? v0 : NEG_SLOPE * v0;
        v1 = (v1 > 0.0f) ? v1 : NEG_SLOPE * v1;
        float p = v0 * a0;
        float q = v1 * a1;
        #pragma unroll
        for (int o = 16; o; o >>= 1) {
            p += __shfl_xor_sync(0xffffffffu, p, o);
            q += __shfl_xor_sync(0xffffffffu, q, o);
        }
        m0 = fmaxf(m0, p);
        m1 = fmaxf(m1, q);
        if (lane == 0) { g_logit[2 * k] = p; g_logit[2 * k + 1] = q; }
    }
    __threadfence_block();

    // pass 2: exp-sum + weighted feature accumulation (division folded out)
    float s0 = 0.0f, s1 = 0.0f, acc0 = 0.0f, acc1 = 0.0f;
    for (int k = beg; k < end; k++) {
        const int s  = g_srcs[k];
        const float e0 = __expf(g_logit[2 * k]     - m0);
        const float e1 = __expf(g_logit[2 * k + 1] - m1);
        s0 += e0;
        s1 += e1;
        acc0 = fmaf(g_xl[s * HC + lane],      e0, acc0);
        acc1 = fmaf(g_xl[s * HC + 32 + lane], e1, acc1);
    }
    const float h0 = acc0 / s0 + bias[lane];
    const float h1 = acc1 / s1 + bias[32 + lane];
    g_h[i * HC + lane]      = h0;
    g_h[i * HC + 32 + lane] = h1;

    // precompute scalar projections for the GraphConv score
    float r = h0 * w_rel[lane]  + h1 * w_rel[32 + lane];
    float t = h0 * w_root[lane] + h1 * w_root[32 + lane];
    #pragma unroll
    for (int o = 16; o; o >>= 1) {
        r += __shfl_xor_sync(0xffffffffu, r, o);
        t += __shfl_xor_sync(0xffffffffu, t, o);
    }
    if (lane == 0) {
        g_hs[i]    = r;
        g_score[i] = t + b_score[0];
    }
}

// ---------------- K8: score += sum_{dst=i} hs[src]  (original edges only) ----
__global__ void k_aggr(const int* __restrict__ ei) {
    int e = blockIdx.x * blockDim.x + threadIdx.x;
    if (e < NE) atomicAdd(&g_score[ei[NE + e]], g_hs[ei[e]]);
}

// ---------------- K9: per-graph score max ------------------------------------
__global__ void k_gmax(const int* __restrict__ batch) {
    int i = blockIdx.x * blockDim.x + threadIdx.x;
    if (i < NN) atomicMaxFloat(&g_gmax[batch[i]], g_score[i]);
}

// ---------------- K10: weighted pooling accumulation (warp per node) ---------
__global__ void __launch_bounds__(256) k_gacc(const int* __restrict__ batch) {
    const int w    = (blockIdx.x * blockDim.x + threadIdx.x) >> 5;
    const int lane = threadIdx.x & 31;
    if (w >= NN) return;
    const int   b = batch[w];
    const float e = __expf(g_score[w] - g_gmax[b]);
    if (lane == 0) {
        atomicAdd(&g_gsum[b], e);
        atomicAdd(&g_cnt[b], 1);
    }
    atomicAdd(&g_gacc[b * HC + lane],      g_h[w * HC + lane]      * e);
    atomicAdd(&g_gacc[b * HC + 32 + lane], g_h[w * HC + 32 + lane] * e);
}

// ---------------- K11: finalize  out = add * (1 + 1/cnt) ----------------------
__global__ void k_out(float* __restrict__ out) {
    int idx = blockIdx.x * blockDim.x + threadIdx.x;
    if (idx < NG * HC) {
        const int g = idx >> 6;
        const float s = g_gsum[g];
        float r = 0.0f;
        if (s > 0.0f) {
            const float add = g_gacc[idx] / s;
            const float c   = (float)g_cnt[g];
            r = add * (1.0f + 1.0f / fmaxf(c, 1.0f));
        }
        out[idx] = r;
    }
}

// ---------------- launch ------------------------------------------------------
extern "C" void kernel_launch(void* const* d_in, const int* in_sizes, int n_in,
                              void* d_out, int out_size) {
    const float* x      = (const float*)d_in[0];
    const int*   ei     = (const int*)  d_in[1];   // [2, E]: src then dst
    const int*   batch  = (const int*)  d_in[2];
    const float* Wl     = (const float*)d_in[3];
    const float* Wr     = (const float*)d_in[4];
    const float* att    = (const float*)d_in[5];
    const float* bias   = (const float*)d_in[6];
    const float* w_rel  = (const float*)d_in[7];
    const float* w_root = (const float*)d_in[8];
    const float* b_sc   = (const float*)d_in[9];
    float* out = (float*)d_out;

    k_init   <<<512, 256>>>();
    k_gemm   <<<NN / 32, 256>>>(x, Wl, Wr);
    k_hist   <<<(NE + 255) / 256, 256>>>(ei);
    k_scan1  <<<98, 1024>>>();
    k_scan2  <<<1, 128>>>();
    k_scan3  <<<(NN + 255) / 256, 256>>>();
    k_scatter<<<(NEX + 255) / 256, 256>>>(ei);
    k_attn   <<<NN / 8, 256>>>(att, bias, w_rel, w_root, b_sc);
    k_aggr   <<<(NE + 255) / 256, 256>>>(ei);
    k_gmax   <<<(NN + 255) / 256, 256>>>(batch);
    k_gacc   <<<NN / 8, 256>>>(batch);
    k_out    <<<(NG * HC + 255) / 256, 256>>>(out);
}

// round 14
// speedup vs baseline: 1.0007x; 1.0007x over previous
#include <cuda_runtime.h>
#include <cuda_bf16.h>

#define NN   100000
#define NE   1000000
#define NEX  (NE + NN)      // edges + self loops
#define NG   2048
#define FIN  128
#define HC   64
#define NEG_SLOPE 0.2f

// ---------------- scratch (device globals; no cudaMalloc allowed) -----------
__device__ float g_xl[NN * HC];        // lin_l(x)  [N,64]
__device__ float g_xr[NN * HC];        // lin_r(x)  [N,64]
__device__ int   g_off[NN + 1];        // degree -> exclusive offsets (in place)
__device__ int   g_cur[NN];            // scatter cursors
__device__ int   g_srcs[NEX];          // CSR: src node per incoming edge slot
__device__ float g_logit[NEX * 2];     // per-edge per-head attention logits
__device__ float g_h[NN * HC];         // conv output
__device__ float g_hs[NN];             // h . w_rel
__device__ float g_score[NN];          // SAG score
__device__ float g_gmax[NG];
__device__ float g_gsum[NG];
__device__ int   g_cnt[NG];
__device__ float g_gacc[NG * HC];
__device__ int   g_bsum[128];          // scan block sums

__device__ __forceinline__ void atomicMaxFloat(float* addr, float v) {
    if (v >= 0.0f) atomicMax((int*)addr, __float_as_int(v));
    else           atomicMin((unsigned int*)addr, __float_as_uint(v));
}

// ---------------- K0: init ---------------------------------------------------
__global__ void k_init() {
    int i = blockIdx.x * blockDim.x + threadIdx.x;
    if (i < NN) g_off[i] = 1;                 // self loop pre-counted
    if (i < NG) {
        g_gmax[i] = __int_as_float(0xff800000);  // -inf
        g_gsum[i] = 0.0f;
        g_cnt[i]  = 0;
    }
    if (i < NG * HC) g_gacc[i] = 0.0f;
    if (i == 0) g_off[NN] = NEX;
}

// ---------------- K1: xl = x@W_l, xr = x@W_r ---------------------------------
// block: 256 thr; tile: 32 rows x 128 output cols (cols 0-63 -> xl, 64-127 -> xr)
// thread (cg = tid&31, rg = tid>>5): 4 rows x 4 cols register tile.
__global__ void __launch_bounds__(256) k_gemm(const float* __restrict__ x,
                                              const float* __restrict__ Wl,
                                              const float* __restrict__ Wr) {
    __shared__ float sx[32 * 128];   // 16KB
    const int tid = threadIdx.x;
    const int cg  = tid & 31;
    const int rg  = tid >> 5;
    const float* Wmat = (cg < 16) ? Wl : Wr;
    float* outp = (cg < 16) ? g_xl : g_xr;
    const int col = (cg & 15) * 4;

    for (int tile = blockIdx.x; tile < NN / 32; tile += gridDim.x) {
        const int row0 = tile * 32;
        __syncthreads();
        {   // stage x tile (coalesced float4)
            const float4* xg = (const float4*)(x + (size_t)row0 * FIN);
            float4* sx4 = (float4*)sx;
            #pragma unroll
            for (int idx = tid; idx < 1024; idx += 256) sx4[idx] = xg[idx];
        }
        __syncthreads();

        float acc[4][4];
        #pragma unroll
        for (int j = 0; j < 4; j++)
            #pragma unroll
            for (int c = 0; c < 4; c++) acc[j][c] = 0.0f;

        #pragma unroll 8
        for (int k = 0; k < FIN; k++) {
            const float4 w = __ldg((const float4*)(Wmat + k * HC + col));
            #pragma unroll
            for (int j = 0; j < 4; j++) {
                const float xv = sx[(rg * 4 + j) * FIN + k];   // warp broadcast
                acc[j][0] = fmaf(xv, w.x, acc[j][0]);
                acc[j][1] = fmaf(xv, w.y, acc[j][1]);
                acc[j][2] = fmaf(xv, w.z, acc[j][2]);
                acc[j][3] = fmaf(xv, w.w, acc[j][3]);
            }
        }
        #pragma unroll
        for (int j = 0; j < 4; j++) {
            const int row = row0 + rg * 4 + j;
            *((float4*)(outp + (size_t)row * HC + col)) =
                make_float4(acc[j][0], acc[j][1], acc[j][2], acc[j][3]);
        }
    }
}

// ---------------- K2: in-degree histogram ------------------------------------
__global__ void k_hist(const int* __restrict__ ei) {
    int e = blockIdx.x * blockDim.x + threadIdx.x;
    if (e < NE) atomicAdd(&g_off[ei[NE + e]], 1);
}

// ---------------- K3-K5: exclusive scan of degrees ---------------------------
__global__ void __launch_bounds__(1024) k_scan1() {
    __shared__ int sm[1024];
    const int tid = threadIdx.x;
    const int gid = blockIdx.x * 1024 + tid;
    int v = (gid < NN) ? g_off[gid] : 0;
    sm[tid] = v;
    __syncthreads();
    #pragma unroll
    for (int o = 1; o < 1024; o <<= 1) {
        int t = (tid >= o) ? sm[tid - o] : 0;
        __syncthreads();
        sm[tid] += t;
        __syncthreads();
    }
    if (gid < NN) g_off[gid] = sm[tid] - v;        // exclusive
    if (tid == 1023) g_bsum[blockIdx.x] = sm[1023];
}

__global__ void k_scan2() {
    __shared__ int sm[128];
    const int tid = threadIdx.x;
    int v = (tid < 98) ? g_bsum[tid] : 0;
    sm[tid] = v;
    __syncthreads();
    #pragma unroll
    for (int o = 1; o < 128; o <<= 1) {
        int t = (tid >= o) ? sm[tid - o] : 0;
        __syncthreads();
        sm[tid] += t;
        __syncthreads();
    }
    if (tid < 98) g_bsum[tid] = sm[tid] - v;       // exclusive block offsets
}

__global__ void k_scan3() {
    int gid = blockIdx.x * blockDim.x + threadIdx.x;
    if (gid < NN) {
        int o = g_off[gid] + g_bsum[gid >> 10];
        g_off[gid] = o;
        g_cur[gid] = o;
    }
}

// ---------------- K6: scatter edges into dst-CSR -----------------------------
__global__ void k_scatter(const int* __restrict__ ei) {
    int e = blockIdx.x * blockDim.x + threadIdx.x;
    if (e < NEX) {
        int s, d;
        if (e < NE) { s = ei[e]; d = ei[NE + e]; }
        else        { s = d = e - NE; }            // self loop
        int pos = atomicAdd(&g_cur[d], 1);
        g_srcs[pos] = s;
    }
}

// ---------------- K7: GATv2 attention, warp per dst node ---------------------
// lane l owns features (h=0,c=l) and (h=1,c=l) i.e. flat idx l and l+32.
__global__ void __launch_bounds__(256) k_attn(const float* __restrict__ att,
                                              const float* __restrict__ bias,
                                              const float* __restrict__ w_rel,
                                              const float* __restrict__ w_root,
                                              const float* __restrict__ b_score) {
    const int w    = (blockIdx.x * blockDim.x + threadIdx.x) >> 5;
    const int lane = threadIdx.x & 31;
    if (w >= NN) return;
    const int i   = w;
    const int beg = g_off[i];
    const int end = g_off[i + 1];

    const float xr0 = g_xr[i * HC + lane];
    const float xr1 = g_xr[i * HC + 32 + lane];
    const float a0  = att[lane];
    const float a1  = att[32 + lane];

    float m0 = -INFINITY, m1 = -INFINITY;
    // pass 1: logits + per-head max
    for (int k = beg; k < end; k++) {
        const int s = g_srcs[k];
        float v0 = g_xl[s * HC + lane]      + xr0;
        float v1 = g_xl[s * HC + 32 + lane] + xr1;
        v0 = (v0 > 0.0f) ? v0 : NEG_SLOPE * v0;
        v1 = (v1 > 0.0f) ? v1 : NEG_SLOPE * v1;
        float p = v0 * a0;
        float q = v1 * a1;
        #pragma unroll
        for (int o = 16; o; o >>= 1) {
            p += __shfl_xor_sync(0xffffffffu, p, o);
            q += __shfl_xor_sync(0xffffffffu, q, o);
        }
        m0 = fmaxf(m0, p);
        m1 = fmaxf(m1, q);
        if (lane == 0) { g_logit[2 * k] = p; g_logit[2 * k + 1] = q; }
    }
    __threadfence_block();

    // pass 2: exp-sum + weighted feature accumulation (division folded out)
    float s0 = 0.0f, s1 = 0.0f, acc0 = 0.0f, acc1 = 0.0f;
    for (int k = beg; k < end; k++) {
        const int s  = g_srcs[k];
        const float e0 = __expf(g_logit[2 * k]     - m0);
        const float e1 = __expf(g_logit[2 * k + 1] - m1);
        s0 += e0;
        s1 += e1;
        acc0 = fmaf(g_xl[s * HC + lane],      e0, acc0);
        acc1 = fmaf(g_xl[s * HC + 32 + lane], e1, acc1);
    }
    const float h0 = acc0 / s0 + bias[lane];
    const float h1 = acc1 / s1 + bias[32 + lane];
    g_h[i * HC + lane]      = h0;
    g_h[i * HC + 32 + lane] = h1;

    // precompute scalar projections for the GraphConv score
    float r = h0 * w_rel[lane]  + h1 * w_rel[32 + lane];
    float t = h0 * w_root[lane] + h1 * w_root[32 + lane];
    #pragma unroll
    for (int o = 16; o; o >>= 1) {
        r += __shfl_xor_sync(0xffffffffu, r, o);
        t += __shfl_xor_sync(0xffffffffu, t, o);
    }
    if (lane == 0) {
        g_hs[i]    = r;
        g_score[i] = t + b_score[0];
    }
}

// ---------------- K8: score += sum_{dst=i} hs[src]  (original edges only) ----
__global__ void k_aggr(const int* __restrict__ ei) {
    int e = blockIdx.x * blockDim.x + threadIdx.x;
    if (e < NE) atomicAdd(&g_score[ei[NE + e]], g_hs[ei[e]]);
}

// ---------------- K9: per-graph score max ------------------------------------
__global__ void k_gmax(const int* __restrict__ batch) {
    int i = blockIdx.x * blockDim.x + threadIdx.x;
    if (i < NN) atomicMaxFloat(&g_gmax[batch[i]], g_score[i]);
}

// ---------------- K10: weighted pooling accumulation (warp per node) ---------
__global__ void __launch_bounds__(256) k_gacc(const int* __restrict__ batch) {
    const int w    = (blockIdx.x * blockDim.x + threadIdx.x) >> 5;
    const int lane = threadIdx.x & 31;
    if (w >= NN) return;
    const int   b = batch[w];
    const float e = __expf(g_score[w] - g_gmax[b]);
    if (lane == 0) {
        atomicAdd(&g_gsum[b], e);
        atomicAdd(&g_cnt[b], 1);
    }
    atomicAdd(&g_gacc[b * HC + lane],      g_h[w * HC + lane]      * e);
    atomicAdd(&g_gacc[b * HC + 32 + lane], g_h[w * HC + 32 + lane] * e);
}

// ---------------- K11: finalize  out = add * (1 + 1/cnt) ----------------------
__global__ void k_out(float* __restrict__ out) {
    int idx = blockIdx.x * blockDim.x + threadIdx.x;
    if (idx < NG * HC) {
        const int g = idx >> 6;
        const float s = g_gsum[g];
        float r = 0.0f;
        if (s > 0.0f) {
            const float add = g_gacc[idx] / s;
            const float c   = (float)g_cnt[g];
            r = add * (1.0f + 1.0f / fmaxf(c, 1.0f));
        }
        out[idx] = r;
    }
}

// ---------------- launch ------------------------------------------------------
extern "C" void kernel_launch(void* const* d_in, const int* in_sizes, int n_in,
                              void* d_out, int out_size) {
    const float* x      = (const float*)d_in[0];
    const int*   ei     = (const int*)  d_in[1];   // [2, E]: src then dst
    const int*   batch  = (const int*)  d_in[2];
    const float* Wl     = (const float*)d_in[3];
    const float* Wr     = (const float*)d_in[4];
    const float* att    = (const float*)d_in[5];
    const float* bias   = (const float*)d_in[6];
    const float* w_rel  = (const float*)d_in[7];
    const float* w_root = (const float*)d_in[8];
    const float* b_sc   = (const float*)d_in[9];
    float* out = (float*)d_out;

    k_init   <<<512, 256>>>();
    k_gemm   <<<NN / 32, 256>>>(x, Wl, Wr);
    k_hist   <<<(NE + 255) / 256, 256>>>(ei);
    k_scan1  <<<98, 1024>>>();
    k_scan2  <<<1, 128>>>();
    k_scan3  <<<(NN + 255) / 256, 256>>>();
    k_scatter<<<(NEX + 255) / 256, 256>>>(ei);
    k_attn   <<<NN / 8, 256>>>(att, bias, w_rel, w_root, b_sc);
    k_aggr   <<<(NE + 255) / 256, 256>>>(ei);
    k_gmax   <<<(NN + 255) / 256, 256>>>(batch);
    k_gacc   <<<NN / 8, 256>>>(batch);
    k_out    <<<(NG * HC + 255) / 256, 256>>>(out);
}

// round 15
// speedup vs baseline: 1.0895x; 1.0887x over previous
#include <cuda_runtime.h>
#include <cuda_bf16.h>

#define NN   100000
#define NE   1000000
#define NEX  (NE + NN)      // edges + self loops
#define NG   2048
#define FIN  128
#define HC   64
#define NEG_SLOPE 0.2f

// ---------------- scratch (device globals; no cudaMalloc allowed) -----------
__device__ float  g_xl[NN * HC];        // lin_l(x)  [N,64]
__device__ float  g_xr[NN * HC];        // lin_r(x)  [N,64]
__device__ int    g_off[NN + 1];        // degree -> exclusive offsets (in place)
__device__ int    g_cur[NN];            // scatter cursors
__device__ int    g_srcs[NEX];          // CSR: src node per incoming edge slot
__device__ float  g_h[NN * HC];         // conv output
__device__ float  g_hs[NN];             // h . w_rel
__device__ float  g_score[NN];          // SAG score
__device__ float  g_escore[NN];         // exp(score - gmax[batch])
__device__ float  g_gmax[NG];
__device__ float  g_gsum[NG];
__device__ int    g_cnt[NG];
__device__ float  g_gacc[NG * HC];
__device__ int    g_bsum[128];          // scan block sums
__device__ float2 g_Wlp[64 * 64];       // W_l packed: [kpair][col] = (W[2kp][c], W[2kp+1][c])
__device__ float2 g_Wrp[64 * 64];       // W_r packed

__device__ __forceinline__ void atomicMaxFloat(float* addr, float v) {
    if (v >= 0.0f) atomicMax((int*)addr, __float_as_int(v));
    else           atomicMin((unsigned int*)addr, __float_as_uint(v));
}

// packed fp32x2 FMA (Blackwell FFMA2 — only reachable via PTX)
__device__ __forceinline__ unsigned long long ffma2(unsigned long long a,
                                                    unsigned long long b,
                                                    unsigned long long c) {
    unsigned long long d;
    asm("fma.rn.f32x2 %0, %1, %2, %3;" : "=l"(d) : "l"(a), "l"(b), "l"(c));
    return d;
}
__device__ __forceinline__ float2 u2f2(unsigned long long v) {
    float2 r;
    asm("mov.b64 {%0, %1}, %2;" : "=f"(r.x), "=f"(r.y) : "l"(v));
    return r;
}

// ---------------- K0: init ---------------------------------------------------
__global__ void k_init() {
    int i = blockIdx.x * blockDim.x + threadIdx.x;
    if (i < NN) g_off[i] = 1;                 // self loop pre-counted
    if (i < NG) {
        g_gmax[i] = __int_as_float(0xff800000);  // -inf
        g_gsum[i] = 0.0f;
        g_cnt[i]  = 0;
    }
    if (i < NG * HC) g_gacc[i] = 0.0f;
    if (i == 0) g_off[NN] = NEX;
}

// ---------------- K0b: pack W into k-pair float2 layout ----------------------
__global__ void k_wpack(const float* __restrict__ Wl, const float* __restrict__ Wr) {
    int idx = blockIdx.x * blockDim.x + threadIdx.x;
    if (idx < 4096) {
        int kp = idx >> 6, c = idx & 63;
        g_Wlp[idx] = make_float2(Wl[(2 * kp) * HC + c], Wl[(2 * kp + 1) * HC + c]);
        g_Wrp[idx] = make_float2(Wr[(2 * kp) * HC + c], Wr[(2 * kp + 1) * HC + c]);
    }
}

// ---------------- K1: xl = x@W_l, xr = x@W_r  (FFMA2 version) ----------------
// block: 256 thr; tile: 32 rows x 128 out cols (cols 0-63 -> xl, 64-127 -> xr)
// thread (cg=tid&31, rg=tid>>5): 4 rows x 4 cols; each FFMA2 lane pair holds
// (even-k, odd-k) partial sums, reduced at the end.
__global__ void __launch_bounds__(256) k_gemm(const float* __restrict__ x) {
    __shared__ float sx[32 * 128];   // 16KB
    const int tid = threadIdx.x;
    const int cg  = tid & 31;
    const int rg  = tid >> 5;
    const float2* Wp = (cg < 16) ? g_Wlp : g_Wrp;
    float* outp = (cg < 16) ? g_xl : g_xr;
    const int col = (cg & 15) * 4;
    const int row0 = blockIdx.x * 32;

    {   // stage x tile (coalesced float4)
        const float4* xg = (const float4*)(x + (size_t)row0 * FIN);
        float4* sx4 = (float4*)sx;
        #pragma unroll
        for (int idx = tid; idx < 1024; idx += 256) sx4[idx] = xg[idx];
    }
    __syncthreads();

    unsigned long long acc[4][4];
    #pragma unroll
    for (int j = 0; j < 4; j++)
        #pragma unroll
        for (int c = 0; c < 4; c++) acc[j][c] = 0ull;

    const unsigned long long* s0 = (const unsigned long long*)&sx[(rg * 4 + 0) * FIN];
    const unsigned long long* s1 = (const unsigned long long*)&sx[(rg * 4 + 1) * FIN];
    const unsigned long long* s2 = (const unsigned long long*)&sx[(rg * 4 + 2) * FIN];
    const unsigned long long* s3 = (const unsigned long long*)&sx[(rg * 4 + 3) * FIN];

    #pragma unroll 4
    for (int kp = 0; kp < 64; kp++) {
        const unsigned long long a0 = s0[kp];
        const unsigned long long a1 = s1[kp];
        const unsigned long long a2 = s2[kp];
        const unsigned long long a3 = s3[kp];
        const ulonglong2* wp = (const ulonglong2*)(Wp + kp * 64 + col);
        const ulonglong2 w01 = wp[0];
        const ulonglong2 w23 = wp[1];
        acc[0][0] = ffma2(a0, w01.x, acc[0][0]);
        acc[0][1] = ffma2(a0, w01.y, acc[0][1]);
        acc[0][2] = ffma2(a0, w23.x, acc[0][2]);
        acc[0][3] = ffma2(a0, w23.y, acc[0][3]);
        acc[1][0] = ffma2(a1, w01.x, acc[1][0]);
        acc[1][1] = ffma2(a1, w01.y, acc[1][1]);
        acc[1][2] = ffma2(a1, w23.x, acc[1][2]);
        acc[1][3] = ffma2(a1, w23.y, acc[1][3]);
        acc[2][0] = ffma2(a2, w01.x, acc[2][0]);
        acc[2][1] = ffma2(a2, w01.y, acc[2][1]);
        acc[2][2] = ffma2(a2, w23.x, acc[2][2]);
        acc[2][3] = ffma2(a2, w23.y, acc[2][3]);
        acc[3][0] = ffma2(a3, w01.x, acc[3][0]);
        acc[3][1] = ffma2(a3, w01.y, acc[3][1]);
        acc[3][2] = ffma2(a3, w23.x, acc[3][2]);
        acc[3][3] = ffma2(a3, w23.y, acc[3][3]);
    }
    #pragma unroll
    for (int j = 0; j < 4; j++) {
        const int row = row0 + rg * 4 + j;
        float2 v0 = u2f2(acc[j][0]);
        float2 v1 = u2f2(acc[j][1]);
        float2 v2 = u2f2(acc[j][2]);
        float2 v3 = u2f2(acc[j][3]);
        *((float4*)(outp + (size_t)row * HC + col)) =
            make_float4(v0.x + v0.y, v1.x + v1.y, v2.x + v2.y, v3.x + v3.y);
    }
}

// ---------------- K2: in-degree histogram ------------------------------------
__global__ void k_hist(const int* __restrict__ ei) {
    int e = blockIdx.x * blockDim.x + threadIdx.x;
    if (e < NE) atomicAdd(&g_off[ei[NE + e]], 1);
}

// ---------------- K3-K5: exclusive scan of degrees ---------------------------
__global__ void __launch_bounds__(1024) k_scan1() {
    __shared__ int sm[1024];
    const int tid = threadIdx.x;
    const int gid = blockIdx.x * 1024 + tid;
    int v = (gid < NN) ? g_off[gid] : 0;
    sm[tid] = v;
    __syncthreads();
    #pragma unroll
    for (int o = 1; o < 1024; o <<= 1) {
        int t = (tid >= o) ? sm[tid - o] : 0;
        __syncthreads();
        sm[tid] += t;
        __syncthreads();
    }
    if (gid < NN) g_off[gid] = sm[tid] - v;        // exclusive
    if (tid == 1023) g_bsum[blockIdx.x] = sm[1023];
}

__global__ void k_scan2() {
    __shared__ int sm[128];
    const int tid = threadIdx.x;
    int v = (tid < 98) ? g_bsum[tid] : 0;
    sm[tid] = v;
    __syncthreads();
    #pragma unroll
    for (int o = 1; o < 128; o <<= 1) {
        int t = (tid >= o) ? sm[tid - o] : 0;
        __syncthreads();
        sm[tid] += t;
        __syncthreads();
    }
    if (tid < 98) g_bsum[tid] = sm[tid] - v;       // exclusive block offsets
}

__global__ void k_scan3() {
    int gid = blockIdx.x * blockDim.x + threadIdx.x;
    if (gid < NN) {
        int o = g_off[gid] + g_bsum[gid >> 10];
        g_off[gid] = o;
        g_cur[gid] = o;
    }
}

// ---------------- K6: scatter edges into dst-CSR -----------------------------
__global__ void k_scatter(const int* __restrict__ ei) {
    int e = blockIdx.x * blockDim.x + threadIdx.x;
    if (e < NEX) {
        int s, d;
        if (e < NE) { s = ei[e]; d = ei[NE + e]; }
        else        { s = d = e - NE; }            // self loop
        int pos = atomicAdd(&g_cur[d], 1);
        g_srcs[pos] = s;
    }
}

// ---------------- K7: GATv2 attention, warp per dst, fused online softmax ----
// lane layout: head h = lane>>4, channels c = (lane&15)*2, (lane&15)*2+1.
// Dot-reduce is a 16-lane butterfly (4 shuffles); softmax is online, so only
// ONE gather pass over xl[src] and no logit spill.
__global__ void __launch_bounds__(256) k_attn(const float* __restrict__ att,
                                              const float* __restrict__ bias,
                                              const float* __restrict__ w_rel,
                                              const float* __restrict__ w_root,
                                              const float* __restrict__ b_score) {
    const int w    = (blockIdx.x * blockDim.x + threadIdx.x) >> 5;
    const int lane = threadIdx.x & 31;
    if (w >= NN) return;
    const int i = w;
    const int f = ((lane >> 4) << 5) + ((lane & 15) << 1);  // flat feature idx (even)

    const float2 xr = *(const float2*)&g_xr[i * HC + f];
    const float2 av = *(const float2*)&att[f];
    const int beg = g_off[i];
    const int end = g_off[i + 1];

    float m = -INFINITY, ssum = 0.0f;
    float ax = 0.0f, ay = 0.0f;

    for (int k = beg; k < end; k++) {
        const int s = g_srcs[k];
        const float2 xl = *(const float2*)&g_xl[s * HC + f];
        float vx = xl.x + xr.x, vy = xl.y + xr.y;
        vx = (vx > 0.0f) ? vx : NEG_SLOPE * vx;
        vy = (vy > 0.0f) ? vy : NEG_SLOPE * vy;
        float p = fmaf(vx, av.x, vy * av.y);
        p += __shfl_xor_sync(0xffffffffu, p, 1);
        p += __shfl_xor_sync(0xffffffffu, p, 2);
        p += __shfl_xor_sync(0xffffffffu, p, 4);
        p += __shfl_xor_sync(0xffffffffu, p, 8);
        // p = head logit (uniform within the 16-lane half-warp)
        if (p > m) {                     // rescale running state
            const float sc = __expf(m - p);
            ssum *= sc; ax *= sc; ay *= sc;
            m = p;
        }
        const float e = __expf(p - m);
        ssum += e;
        ax = fmaf(xl.x, e, ax);
        ay = fmaf(xl.y, e, ay);
    }
    const float inv = 1.0f / ssum;       // degree >= 1 (self loop)
    const float2 bi = *(const float2*)&bias[f];
    const float hx = ax * inv + bi.x;
    const float hy = ay * inv + bi.y;
    *(float2*)&g_h[i * HC + f] = make_float2(hx, hy);

    // scalar projections for the GraphConv score (full 64-wide reduce)
    const float2 wr = *(const float2*)&w_rel[f];
    const float2 wt = *(const float2*)&w_root[f];
    float r = fmaf(hx, wr.x, hy * wr.y);
    float t = fmaf(hx, wt.x, hy * wt.y);
    #pragma unroll
    for (int o = 16; o; o >>= 1) {
        r += __shfl_xor_sync(0xffffffffu, r, o);
        t += __shfl_xor_sync(0xffffffffu, t, o);
    }
    if (lane == 0) {
        g_hs[i]    = r;
        g_score[i] = t + b_score[0];
    }
}

// ---------------- K8: score += sum_{dst=i} hs[src]  (original edges only) ----
__global__ void k_aggr(const int* __restrict__ ei) {
    int e = blockIdx.x * blockDim.x + threadIdx.x;
    if (e < NE) atomicAdd(&g_score[ei[NE + e]], g_hs[ei[e]]);
}

// ---------------- K9: per-graph score max ------------------------------------
__global__ void k_gmax(const int* __restrict__ batch) {
    int i = blockIdx.x * blockDim.x + threadIdx.x;
    if (i < NN) atomicMaxFloat(&g_gmax[batch[i]], g_score[i]);
}

// ---------------- K9b: per-node exp weight + graph sums ----------------------
__global__ void k_escore(const int* __restrict__ batch) {
    int i = blockIdx.x * blockDim.x + threadIdx.x;
    if (i < NN) {
        const int b = batch[i];
        const float e = __expf(g_score[i] - g_gmax[b]);
        g_escore[i] = e;
        atomicAdd(&g_gsum[b], e);
        atomicAdd(&g_cnt[b], 1);
    }
}

// ---------------- K10: weighted pooling, sorted-batch running flush ----------
// block handles 128 consecutive nodes; thread owns feature c = tid&63 and
// strides by 4 over nodes, flushing its partial only when the graph id changes.
__global__ void __launch_bounds__(256) k_gacc(const int* __restrict__ batch) {
    const int c  = threadIdx.x & 63;
    const int g4 = threadIdx.x >> 6;
    const int n0 = blockIdx.x * 128;
    const int n1 = min(n0 + 128, NN);
    int curb = -1;
    float accv = 0.0f;
    for (int n = n0 + g4; n < n1; n += 4) {
        const int b = __ldg(&batch[n]);
        if (b != curb) {
            if (curb >= 0) atomicAdd(&g_gacc[curb * HC + c], accv);
            curb = b;
            accv = 0.0f;
        }
        accv = fmaf(g_h[n * HC + c], g_escore[n], accv);
    }
    if (curb >= 0) atomicAdd(&g_gacc[curb * HC + c], accv);
}

// ---------------- K11: finalize  out = add * (1 + 1/cnt) ----------------------
__global__ void k_out(float* __restrict__ out) {
    int idx = blockIdx.x * blockDim.x + threadIdx.x;
    if (idx < NG * HC) {
        const int g = idx >> 6;
        const float s = g_gsum[g];
        float r = 0.0f;
        if (s > 0.0f) {
            const float add = g_gacc[idx] / s;
            const float c   = (float)g_cnt[g];
            r = add * (1.0f + 1.0f / fmaxf(c, 1.0f));
        }
        out[idx] = r;
    }
}

// ---------------- launch ------------------------------------------------------
extern "C" void kernel_launch(void* const* d_in, const int* in_sizes, int n_in,
                              void* d_out, int out_size) {
    const float* x      = (const float*)d_in[0];
    const int*   ei     = (const int*)  d_in[1];   // [2, E]: src then dst
    const int*   batch  = (const int*)  d_in[2];
    const float* Wl     = (const float*)d_in[3];
    const float* Wr     = (const float*)d_in[4];
    const float* att    = (const float*)d_in[5];
    const float* bias   = (const float*)d_in[6];
    const float* w_rel  = (const float*)d_in[7];
    const float* w_root = (const float*)d_in[8];
    const float* b_sc   = (const float*)d_in[9];
    float* out = (float*)d_out;

    k_init   <<<512, 256>>>();
    k_wpack  <<<16, 256>>>(Wl, Wr);
    k_gemm   <<<NN / 32, 256>>>(x);
    k_hist   <<<(NE + 255) / 256, 256>>>(ei);
    k_scan1  <<<98, 1024>>>();
    k_scan2  <<<1, 128>>>();
    k_scan3  <<<(NN + 255) / 256, 256>>>();
    k_scatter<<<(NEX + 255) / 256, 256>>>(ei);
    k_attn   <<<(NN + 7) / 8, 256>>>(att, bias, w_rel, w_root, b_sc);
    k_aggr   <<<(NE + 255) / 256, 256>>>(ei);
    k_gmax   <<<(NN + 255) / 256, 256>>>(batch);
    k_escore <<<(NN + 255) / 256, 256>>>(batch);
    k_gacc   <<<(NN + 127) / 128, 256>>>(batch);
    k_out    <<<(NG * HC + 255) / 256, 256>>>(out);
}